// round 16
// baseline (speedup 1.0000x reference)
#include <cuda_runtime.h>
#include <cuda_fp16.h>
#include <cstdint>

#define DIM 64
#define MAX_NODES 100000
#define MAX_EDGES 1600000
#define MAX_GRAPHS 1000
#define SCAN_BLK 1024

// ---------------- scratch (device globals; no allocations allowed) ----------
__device__ float   g_agg[(size_t)MAX_NODES * DIM];   // 25.6 MB
__device__ float   g_h1[(size_t)MAX_NODES * DIM];    // conv1 output (fp32, MLP input)
__device__ __half2 g_x16[(size_t)MAX_NODES * 32];    // fp16 copy of x   (gather operand)
__device__ __half2 g_h16[(size_t)MAX_NODES * 32];    // fp16 copy of h1  (gather operand)
__device__ float   g_sums[MAX_GRAPHS * DIM];
__device__ float   g_cnt[MAX_GRAPHS];

__device__ int  g_deg[MAX_NODES];
__device__ int  g_off[MAX_NODES];
__device__ int  g_pos[MAX_NODES];
__device__ int  g_part[256];                         // scan partials (<=98 used)
__device__ int2 g_pack[MAX_EDGES];                   // (src, attr-bits) sorted by dst

// ---------------- zero small stuff ------------------------------------------
__global__ void zero_small(int n) {
    int i = blockIdx.x * blockDim.x + threadIdx.x;
    if (i < n) g_deg[i] = 0;
    if (i < MAX_GRAPHS * DIM) g_sums[i] = 0.f;
    if (i < MAX_GRAPHS) g_cnt[i] = 0.f;
}

// ---------------- x -> fp16 --------------------------------------------------
__global__ void x2half(const float* __restrict__ x, int n32) {
    int i = blockIdx.x * blockDim.x + threadIdx.x;
    if (i < n32) {
        float2 v = reinterpret_cast<const float2*>(x)[i];
        g_x16[i] = __float22half2_rn(v);
    }
}

// ---------------- histogram over dst ----------------------------------------
__global__ void hist_kernel(const int* __restrict__ ei, int E) {
    int e = blockIdx.x * blockDim.x + threadIdx.x;
    if (e < E) atomicAdd(&g_deg[ei[E + e]], 1);
}

// ---------------- 3-phase coalesced exclusive scan ---------------------------
__global__ void scan_p1(int n) {                     // block b sums its 1024 degs
    __shared__ int red[256];
    int b = blockIdx.x, tid = threadIdx.x;
    int base = b * SCAN_BLK;
    int s = 0;
    for (int j = tid; j < SCAN_BLK; j += 256) {
        int idx = base + j;
        s += (idx < n) ? g_deg[idx] : 0;
    }
    red[tid] = s; __syncthreads();
    for (int o = 128; o > 0; o >>= 1) {
        if (tid < o) red[tid] += red[tid + o];
        __syncthreads();
    }
    if (tid == 0) g_part[b] = red[0];
}

__global__ void scan_p2(int nb) {                    // exclusive scan of partials
    __shared__ int sm[256];
    int tid = threadIdx.x;
    sm[tid] = (tid < nb) ? g_part[tid] : 0;
    __syncthreads();
    for (int o = 1; o < 256; o <<= 1) {
        int v = (tid >= o) ? sm[tid - o] : 0;
        __syncthreads();
        sm[tid] += v;
        __syncthreads();
    }
    if (tid < nb) g_part[tid] = (tid > 0) ? sm[tid - 1] : 0;
}

__global__ void scan_p3(int n) {                     // local scan + base -> off/pos
    __shared__ int tps[256];
    int b = blockIdx.x, tid = threadIdx.x;
    int base = b * SCAN_BLK;
    int v[4]; int s = 0;
    #pragma unroll
    for (int j = 0; j < 4; j++) {
        int idx = base + tid * 4 + j;
        v[j] = (idx < n) ? g_deg[idx] : 0;
        s += v[j];
    }
    tps[tid] = s; __syncthreads();
    for (int o = 1; o < 256; o <<= 1) {
        int t = (tid >= o) ? tps[tid - o] : 0;
        __syncthreads();
        tps[tid] += t;
        __syncthreads();
    }
    int run = ((tid > 0) ? tps[tid - 1] : 0) + g_part[b];
    #pragma unroll
    for (int j = 0; j < 4; j++) {
        int idx = base + tid * 4 + j;
        if (idx < n) { g_off[idx] = run; g_pos[idx] = run; run += v[j]; }
    }
}

// ---------------- scatter edges into dst-sorted buckets ---------------------
__global__ void sort_scatter(const int* __restrict__ ei,
                             const float* __restrict__ ea, int E) {
    int e = blockIdx.x * blockDim.x + threadIdx.x;
    if (e >= E) return;
    int src = ei[e];
    int dst = ei[E + e];
    int p = atomicAdd(&g_pos[dst], 1);
    g_pack[p] = make_int2(src, __float_as_int(ea[e]));
}

// ---------------- CSR aggregation (fp16 gather, fp32 accumulate) ------------
// One warp per dst node; lane holds 2 cols. Row gather = 1 cache line (128B).
__global__ __launch_bounds__(128) void csr_agg16(int useH1,
                                                 const float* __restrict__ We,
                                                 const float* __restrict__ be,
                                                 int n) {
    const __half2* __restrict__ X = useH1 ? g_h16 : g_x16;
    int w = (blockIdx.x * blockDim.x + threadIdx.x) >> 5;
    if (w >= n) return;
    int lane = threadIdx.x & 31;

    float2 wv = reinterpret_cast<const float2*>(We)[lane];
    float2 bv = reinterpret_cast<const float2*>(be)[lane];

    int start = g_off[w];
    int deg   = g_deg[w];

    float2 a0 = make_float2(0.f, 0.f), a1 = a0;

    int i = 0;
    for (; i + 4 <= deg; i += 4) {
        int2 p0 = g_pack[start + i + 0];
        int2 p1 = g_pack[start + i + 1];
        int2 p2 = g_pack[start + i + 2];
        int2 p3 = g_pack[start + i + 3];
        __half2 h0 = X[p0.x * 32 + lane];
        __half2 h1 = X[p1.x * 32 + lane];
        __half2 h2 = X[p2.x * 32 + lane];
        __half2 h3 = X[p3.x * 32 + lane];
        float2 x0 = __half22float2(h0);
        float2 x1 = __half22float2(h1);
        float2 x2 = __half22float2(h2);
        float2 x3 = __half22float2(h3);
        float e0 = __int_as_float(p0.y), e1 = __int_as_float(p1.y);
        float e2 = __int_as_float(p2.y), e3 = __int_as_float(p3.y);
        a0.x += fmaxf(x0.x + fmaf(e0, wv.x, bv.x), 0.f);
        a0.y += fmaxf(x0.y + fmaf(e0, wv.y, bv.y), 0.f);
        a1.x += fmaxf(x1.x + fmaf(e1, wv.x, bv.x), 0.f);
        a1.y += fmaxf(x1.y + fmaf(e1, wv.y, bv.y), 0.f);
        a0.x += fmaxf(x2.x + fmaf(e2, wv.x, bv.x), 0.f);
        a0.y += fmaxf(x2.y + fmaf(e2, wv.y, bv.y), 0.f);
        a1.x += fmaxf(x3.x + fmaf(e3, wv.x, bv.x), 0.f);
        a1.y += fmaxf(x3.y + fmaf(e3, wv.y, bv.y), 0.f);
    }
    for (; i < deg; i++) {
        int2 p0 = g_pack[start + i];
        float2 x0 = __half22float2(X[p0.x * 32 + lane]);
        float e0 = __int_as_float(p0.y);
        a0.x += fmaxf(x0.x + fmaf(e0, wv.x, bv.x), 0.f);
        a0.y += fmaxf(x0.y + fmaf(e0, wv.y, bv.y), 0.f);
    }

    float2 acc = make_float2(a0.x + a1.x, a0.y + a1.y);
    *reinterpret_cast<float2*>(g_agg + (size_t)w * DIM + lane * 2) = acc;
}

// ---------------- fused node MLP -------------------------------------------
extern __shared__ float sm_mlp[];
__global__ __launch_bounds__(128) void node_mlp(
    int mode,
    const float* __restrict__ Xext,
    const float* __restrict__ Wa, const float* __restrict__ ba,
    const float* __restrict__ Wb, const float* __restrict__ bb,
    const int* __restrict__ batch,
    int n)
{
    float* Ws0  = sm_mlp;                 // 4096 floats
    float* Ws1  = sm_mlp + 4096;          // 4096 floats
    float* bs   = sm_mlp + 8192;          // 128 floats
    float* tile = sm_mlp + 8320;          // 128 * 65 floats

    const float* X = mode ? g_h1 : Xext;
    int tid  = threadIdx.x;
    int base = blockIdx.x * 128;
    int node = base + tid;

    for (int i = tid; i < 4096; i += 128) { Ws0[i] = Wa[i]; Ws1[i] = Wb[i]; }
    if (tid < 64) { bs[tid] = ba[tid]; bs[64 + tid] = bb[tid]; }

    for (int i = tid; i < 128 * DIM; i += 128) {
        int r = i >> 6, c = i & 63;
        int nd = base + r;
        float v = 0.f;
        if (nd < n) {
            size_t off = (size_t)nd * DIM + c;
            v = X[off] + g_agg[off];
        }
        tile[r * 65 + c] = v;
    }
    __syncthreads();

    float acc[64];

    #pragma unroll
    for (int j = 0; j < 64; j++) acc[j] = bs[j];
    #pragma unroll 4
    for (int k = 0; k < 64; k++) {
        float tk = tile[tid * 65 + k];
        const float4* wrow = reinterpret_cast<const float4*>(Ws0 + k * 64);
        #pragma unroll
        for (int j = 0; j < 16; j++) {
            float4 w = wrow[j];
            acc[4*j+0] = fmaf(tk, w.x, acc[4*j+0]);
            acc[4*j+1] = fmaf(tk, w.y, acc[4*j+1]);
            acc[4*j+2] = fmaf(tk, w.z, acc[4*j+2]);
            acc[4*j+3] = fmaf(tk, w.w, acc[4*j+3]);
        }
    }
    #pragma unroll
    for (int j = 0; j < 64; j++) tile[tid * 65 + j] = fmaxf(acc[j], 0.f);

    #pragma unroll
    for (int j = 0; j < 64; j++) acc[j] = bs[64 + j];
    #pragma unroll 4
    for (int k = 0; k < 64; k++) {
        float tk = tile[tid * 65 + k];
        const float4* wrow = reinterpret_cast<const float4*>(Ws1 + k * 64);
        #pragma unroll
        for (int j = 0; j < 16; j++) {
            float4 w = wrow[j];
            acc[4*j+0] = fmaf(tk, w.x, acc[4*j+0]);
            acc[4*j+1] = fmaf(tk, w.y, acc[4*j+1]);
            acc[4*j+2] = fmaf(tk, w.z, acc[4*j+2]);
            acc[4*j+3] = fmaf(tk, w.w, acc[4*j+3]);
        }
    }
    #pragma unroll
    for (int j = 0; j < 64; j++) acc[j] = fmaxf(acc[j], 0.f);

    if (mode == 0) {
        #pragma unroll
        for (int j = 0; j < 64; j++) tile[tid * 65 + j] = acc[j];
        __syncthreads();
        for (int i = tid; i < 128 * DIM; i += 128) {
            int r = i >> 6, c = i & 63;
            int nd = base + r;
            if (nd < n) g_h1[(size_t)nd * DIM + c] = tile[r * 65 + c];
        }
        // fp16 copy for conv2 gathers
        for (int i = tid; i < 128 * 32; i += 128) {
            int r = i >> 5, c2 = i & 31;
            int nd = base + r;
            if (nd < n) {
                float2 v = make_float2(tile[r * 65 + c2 * 2],
                                       tile[r * 65 + c2 * 2 + 1]);
                g_h16[(size_t)nd * 32 + c2] = __float22half2_rn(v);
            }
        }
    } else {
        if (node < n) {
            int g = batch[node];
            float* s = g_sums + (size_t)g * DIM;
            #pragma unroll
            for (int j = 0; j < 64; j += 4)
                asm volatile("red.global.add.v4.f32 [%0], {%1,%2,%3,%4};"
                             :: "l"(s + j), "f"(acc[j]), "f"(acc[j+1]),
                                "f"(acc[j+2]), "f"(acc[j+3]) : "memory");
            atomicAdd(&g_cnt[g], 1.0f);
        }
    }
}

// ---------------- classifier over graphs -----------------------------------
__global__ void classifier(const float* __restrict__ Wc1, const float* __restrict__ bc1,
                           const float* __restrict__ Wc2, const float* __restrict__ bc2,
                           float* __restrict__ out, int G)
{
    int g = blockIdx.x * blockDim.x + threadIdx.x;
    if (g >= G) return;
    float inv = 1.0f / fmaxf(g_cnt[g], 1.0f);
    float p[64];
    #pragma unroll
    for (int k = 0; k < 64; k++) p[k] = g_sums[g * 64 + k] * inv;
    float o = bc2[0];
    for (int j = 0; j < 64; j++) {
        float u = bc1[j];
        #pragma unroll
        for (int k = 0; k < 64; k++) u = fmaf(p[k], Wc1[k * 64 + j], u);
        o = fmaf(fmaxf(u, 0.f), Wc2[j], o);
    }
    out[g] = o;
}

// ---------------- launch ----------------------------------------------------
extern "C" void kernel_launch(void* const* d_in, const int* in_sizes, int n_in,
                              void* d_out, int out_size) {
    const float* x     = (const float*)d_in[0];
    const int*   ei    = (const int*)d_in[1];
    const float* eattr = (const float*)d_in[2];
    const int*   batch = (const int*)d_in[3];
    const float *W1a = (const float*)d_in[4],  *b1a = (const float*)d_in[5];
    const float *W1b = (const float*)d_in[6],  *b1b = (const float*)d_in[7];
    const float *We1 = (const float*)d_in[8],  *be1 = (const float*)d_in[9];
    const float *W2a = (const float*)d_in[10], *b2a = (const float*)d_in[11];
    const float *W2b = (const float*)d_in[12], *b2b = (const float*)d_in[13];
    const float *We2 = (const float*)d_in[14], *be2 = (const float*)d_in[15];
    const float *Wc1 = (const float*)d_in[16], *bc1 = (const float*)d_in[17];
    const float *Wc2 = (const float*)d_in[18], *bc2 = (const float*)d_in[19];
    float* out = (float*)d_out;

    int N = in_sizes[0] / DIM;
    int E = in_sizes[2];
    int G = out_size;

    const int SMEM = (4096 * 2 + 128 + 128 * 65) * (int)sizeof(float);  // ~66.5 KB
    cudaFuncSetAttribute(node_mlp, cudaFuncAttributeMaxDynamicSharedMemorySize, SMEM);

    int node_blocks = (N + 127) / 128;
    int agg_blocks  = (N * 32 + 127) / 128;
    int e_blocks    = (E + 255) / 256;
    int nb          = (N + SCAN_BLK - 1) / SCAN_BLK;   // 98

    // ---- build dst-sorted CSR + fp16 x copy (shared by both convs) ----
    zero_small<<<(N + 255) / 256, 256>>>(N);
    x2half<<<(N * 32 + 255) / 256, 256>>>(x, N * 32);
    hist_kernel<<<e_blocks, 256>>>(ei, E);
    scan_p1<<<nb, 256>>>(N);
    scan_p2<<<1, 256>>>(nb);
    scan_p3<<<nb, 256>>>(N);
    sort_scatter<<<e_blocks, 256>>>(ei, eattr, E);

    // conv1
    csr_agg16<<<agg_blocks, 128>>>(0, We1, be1, N);
    node_mlp<<<node_blocks, 128, SMEM>>>(0, x, W1a, b1a, W1b, b1b, batch, N);
    // conv2 (+ fused mean-pool sums)
    csr_agg16<<<agg_blocks, 128>>>(1, We2, be2, N);
    node_mlp<<<node_blocks, 128, SMEM>>>(1, x, W2a, b2a, W2b, b2b, batch, N);
    // classifier
    classifier<<<(G + 127) / 128, 128>>>(Wc1, bc1, Wc2, bc2, out, G);
}

// round 17
// speedup vs baseline: 1.0034x; 1.0034x over previous
#include <cuda_runtime.h>
#include <cuda_fp16.h>
#include <cstdint>

#define DIM 64
#define MAX_NODES 100000
#define MAX_EDGES 1600000
#define MAX_GRAPHS 1000
#define SCAN_BLK 1024

// ---------------- scratch (device globals; no allocations allowed) ----------
__device__ float   g_agg[(size_t)MAX_NODES * DIM];   // 25.6 MB
__device__ float   g_h1[(size_t)MAX_NODES * DIM];    // conv1 output (fp32, MLP input)
__device__ __half2 g_x16[(size_t)MAX_NODES * 32];    // fp16 copy of x   (gather operand)
__device__ __half2 g_h16[(size_t)MAX_NODES * 32];    // fp16 copy of h1  (gather operand)
__device__ float   g_sums[MAX_GRAPHS * DIM];
__device__ float   g_cnt[MAX_GRAPHS];

__device__ int  g_deg[MAX_NODES];
__device__ int  g_off[MAX_NODES];
__device__ int  g_pos[MAX_NODES];
__device__ int  g_part[256];                         // scan partials (<=98 used)
__device__ int2 g_pack[MAX_EDGES];                   // (src, attr-bits) sorted by dst

// ---------------- zero small stuff ------------------------------------------
__global__ void zero_small(int n) {
    int i = blockIdx.x * blockDim.x + threadIdx.x;
    if (i < n) g_deg[i] = 0;
    if (i < MAX_GRAPHS * DIM) g_sums[i] = 0.f;
    if (i < MAX_GRAPHS) g_cnt[i] = 0.f;
}

// ---------------- x -> fp16 --------------------------------------------------
__global__ void x2half(const float* __restrict__ x, int n32) {
    int i = blockIdx.x * blockDim.x + threadIdx.x;
    if (i < n32) {
        float2 v = reinterpret_cast<const float2*>(x)[i];
        g_x16[i] = __float22half2_rn(v);
    }
}

// ---------------- histogram over dst ----------------------------------------
__global__ void hist_kernel(const int* __restrict__ ei, int E) {
    int e = blockIdx.x * blockDim.x + threadIdx.x;
    if (e < E) atomicAdd(&g_deg[ei[E + e]], 1);
}

// ---------------- 3-phase coalesced exclusive scan ---------------------------
__global__ void scan_p1(int n) {                     // block b sums its 1024 degs
    __shared__ int red[256];
    int b = blockIdx.x, tid = threadIdx.x;
    int base = b * SCAN_BLK;
    int s = 0;
    for (int j = tid; j < SCAN_BLK; j += 256) {
        int idx = base + j;
        s += (idx < n) ? g_deg[idx] : 0;
    }
    red[tid] = s; __syncthreads();
    for (int o = 128; o > 0; o >>= 1) {
        if (tid < o) red[tid] += red[tid + o];
        __syncthreads();
    }
    if (tid == 0) g_part[b] = red[0];
}

__global__ void scan_p2(int nb) {                    // exclusive scan of partials
    __shared__ int sm[256];
    int tid = threadIdx.x;
    sm[tid] = (tid < nb) ? g_part[tid] : 0;
    __syncthreads();
    for (int o = 1; o < 256; o <<= 1) {
        int v = (tid >= o) ? sm[tid - o] : 0;
        __syncthreads();
        sm[tid] += v;
        __syncthreads();
    }
    if (tid < nb) g_part[tid] = (tid > 0) ? sm[tid - 1] : 0;
}

__global__ void scan_p3(int n) {                     // local scan + base -> off/pos
    __shared__ int tps[256];
    int b = blockIdx.x, tid = threadIdx.x;
    int base = b * SCAN_BLK;
    int v[4]; int s = 0;
    #pragma unroll
    for (int j = 0; j < 4; j++) {
        int idx = base + tid * 4 + j;
        v[j] = (idx < n) ? g_deg[idx] : 0;
        s += v[j];
    }
    tps[tid] = s; __syncthreads();
    for (int o = 1; o < 256; o <<= 1) {
        int t = (tid >= o) ? tps[tid - o] : 0;
        __syncthreads();
        tps[tid] += t;
        __syncthreads();
    }
    int run = ((tid > 0) ? tps[tid - 1] : 0) + g_part[b];
    #pragma unroll
    for (int j = 0; j < 4; j++) {
        int idx = base + tid * 4 + j;
        if (idx < n) { g_off[idx] = run; g_pos[idx] = run; run += v[j]; }
    }
}

// ---------------- scatter edges into dst-sorted buckets ---------------------
__global__ void sort_scatter(const int* __restrict__ ei,
                             const float* __restrict__ ea, int E) {
    int e = blockIdx.x * blockDim.x + threadIdx.x;
    if (e >= E) return;
    int src = ei[e];
    int dst = ei[E + e];
    int p = atomicAdd(&g_pos[dst], 1);
    g_pack[p] = make_int2(src, __float_as_int(ea[e]));
}

// ---------------- CSR aggregation (fp16 gather, fp32 accumulate) ------------
// One warp per dst node; lane holds 2 cols. Row gather = 1 cache line (128B).
__global__ __launch_bounds__(128) void csr_agg16(int useH1,
                                                 const float* __restrict__ We,
                                                 const float* __restrict__ be,
                                                 int n) {
    const __half2* __restrict__ X = useH1 ? g_h16 : g_x16;
    int w = (blockIdx.x * blockDim.x + threadIdx.x) >> 5;
    if (w >= n) return;
    int lane = threadIdx.x & 31;

    float2 wv = reinterpret_cast<const float2*>(We)[lane];
    float2 bv = reinterpret_cast<const float2*>(be)[lane];

    int start = g_off[w];
    int deg   = g_deg[w];

    float2 a0 = make_float2(0.f, 0.f), a1 = a0;

    int i = 0;
    for (; i + 4 <= deg; i += 4) {
        int2 p0 = g_pack[start + i + 0];
        int2 p1 = g_pack[start + i + 1];
        int2 p2 = g_pack[start + i + 2];
        int2 p3 = g_pack[start + i + 3];
        __half2 h0 = X[p0.x * 32 + lane];
        __half2 h1 = X[p1.x * 32 + lane];
        __half2 h2 = X[p2.x * 32 + lane];
        __half2 h3 = X[p3.x * 32 + lane];
        float2 x0 = __half22float2(h0);
        float2 x1 = __half22float2(h1);
        float2 x2 = __half22float2(h2);
        float2 x3 = __half22float2(h3);
        float e0 = __int_as_float(p0.y), e1 = __int_as_float(p1.y);
        float e2 = __int_as_float(p2.y), e3 = __int_as_float(p3.y);
        a0.x += fmaxf(x0.x + fmaf(e0, wv.x, bv.x), 0.f);
        a0.y += fmaxf(x0.y + fmaf(e0, wv.y, bv.y), 0.f);
        a1.x += fmaxf(x1.x + fmaf(e1, wv.x, bv.x), 0.f);
        a1.y += fmaxf(x1.y + fmaf(e1, wv.y, bv.y), 0.f);
        a0.x += fmaxf(x2.x + fmaf(e2, wv.x, bv.x), 0.f);
        a0.y += fmaxf(x2.y + fmaf(e2, wv.y, bv.y), 0.f);
        a1.x += fmaxf(x3.x + fmaf(e3, wv.x, bv.x), 0.f);
        a1.y += fmaxf(x3.y + fmaf(e3, wv.y, bv.y), 0.f);
    }
    for (; i < deg; i++) {
        int2 p0 = g_pack[start + i];
        float2 x0 = __half22float2(X[p0.x * 32 + lane]);
        float e0 = __int_as_float(p0.y);
        a0.x += fmaxf(x0.x + fmaf(e0, wv.x, bv.x), 0.f);
        a0.y += fmaxf(x0.y + fmaf(e0, wv.y, bv.y), 0.f);
    }

    float2 acc = make_float2(a0.x + a1.x, a0.y + a1.y);
    *reinterpret_cast<float2*>(g_agg + (size_t)w * DIM + lane * 2) = acc;
}

// ---------------- fused node MLP -------------------------------------------
extern __shared__ float sm_mlp[];
__global__ __launch_bounds__(128) void node_mlp(
    int mode,
    const float* __restrict__ Xext,
    const float* __restrict__ Wa, const float* __restrict__ ba,
    const float* __restrict__ Wb, const float* __restrict__ bb,
    const int* __restrict__ batch,
    int n)
{
    float* Ws0  = sm_mlp;                 // 4096 floats
    float* Ws1  = sm_mlp + 4096;          // 4096 floats
    float* bs   = sm_mlp + 8192;          // 128 floats
    float* tile = sm_mlp + 8320;          // 128 * 65 floats

    const float* X = mode ? g_h1 : Xext;
    int tid  = threadIdx.x;
    int base = blockIdx.x * 128;
    int node = base + tid;

    for (int i = tid; i < 4096; i += 128) { Ws0[i] = Wa[i]; Ws1[i] = Wb[i]; }
    if (tid < 64) { bs[tid] = ba[tid]; bs[64 + tid] = bb[tid]; }

    for (int i = tid; i < 128 * DIM; i += 128) {
        int r = i >> 6, c = i & 63;
        int nd = base + r;
        float v = 0.f;
        if (nd < n) {
            size_t off = (size_t)nd * DIM + c;
            v = X[off] + g_agg[off];
        }
        tile[r * 65 + c] = v;
    }
    __syncthreads();

    float acc[64];

    #pragma unroll
    for (int j = 0; j < 64; j++) acc[j] = bs[j];
    #pragma unroll 4
    for (int k = 0; k < 64; k++) {
        float tk = tile[tid * 65 + k];
        const float4* wrow = reinterpret_cast<const float4*>(Ws0 + k * 64);
        #pragma unroll
        for (int j = 0; j < 16; j++) {
            float4 w = wrow[j];
            acc[4*j+0] = fmaf(tk, w.x, acc[4*j+0]);
            acc[4*j+1] = fmaf(tk, w.y, acc[4*j+1]);
            acc[4*j+2] = fmaf(tk, w.z, acc[4*j+2]);
            acc[4*j+3] = fmaf(tk, w.w, acc[4*j+3]);
        }
    }
    #pragma unroll
    for (int j = 0; j < 64; j++) tile[tid * 65 + j] = fmaxf(acc[j], 0.f);

    #pragma unroll
    for (int j = 0; j < 64; j++) acc[j] = bs[64 + j];
    #pragma unroll 4
    for (int k = 0; k < 64; k++) {
        float tk = tile[tid * 65 + k];
        const float4* wrow = reinterpret_cast<const float4*>(Ws1 + k * 64);
        #pragma unroll
        for (int j = 0; j < 16; j++) {
            float4 w = wrow[j];
            acc[4*j+0] = fmaf(tk, w.x, acc[4*j+0]);
            acc[4*j+1] = fmaf(tk, w.y, acc[4*j+1]);
            acc[4*j+2] = fmaf(tk, w.z, acc[4*j+2]);
            acc[4*j+3] = fmaf(tk, w.w, acc[4*j+3]);
        }
    }
    #pragma unroll
    for (int j = 0; j < 64; j++) acc[j] = fmaxf(acc[j], 0.f);

    if (mode == 0) {
        #pragma unroll
        for (int j = 0; j < 64; j++) tile[tid * 65 + j] = acc[j];
        __syncthreads();
        for (int i = tid; i < 128 * DIM; i += 128) {
            int r = i >> 6, c = i & 63;
            int nd = base + r;
            if (nd < n) g_h1[(size_t)nd * DIM + c] = tile[r * 65 + c];
        }
        // fp16 copy for conv2 gathers
        for (int i = tid; i < 128 * 32; i += 128) {
            int r = i >> 5, c2 = i & 31;
            int nd = base + r;
            if (nd < n) {
                float2 v = make_float2(tile[r * 65 + c2 * 2],
                                       tile[r * 65 + c2 * 2 + 1]);
                g_h16[(size_t)nd * 32 + c2] = __float22half2_rn(v);
            }
        }
    } else {
        if (node < n) {
            int g = batch[node];
            float* s = g_sums + (size_t)g * DIM;
            #pragma unroll
            for (int j = 0; j < 64; j += 4)
                asm volatile("red.global.add.v4.f32 [%0], {%1,%2,%3,%4};"
                             :: "l"(s + j), "f"(acc[j]), "f"(acc[j+1]),
                                "f"(acc[j+2]), "f"(acc[j+3]) : "memory");
            atomicAdd(&g_cnt[g], 1.0f);
        }
    }
}

// ---------------- classifier over graphs -----------------------------------
__global__ void classifier(const float* __restrict__ Wc1, const float* __restrict__ bc1,
                           const float* __restrict__ Wc2, const float* __restrict__ bc2,
                           float* __restrict__ out, int G)
{
    int g = blockIdx.x * blockDim.x + threadIdx.x;
    if (g >= G) return;
    float inv = 1.0f / fmaxf(g_cnt[g], 1.0f);
    float p[64];
    #pragma unroll
    for (int k = 0; k < 64; k++) p[k] = g_sums[g * 64 + k] * inv;
    float o = bc2[0];
    for (int j = 0; j < 64; j++) {
        float u = bc1[j];
        #pragma unroll
        for (int k = 0; k < 64; k++) u = fmaf(p[k], Wc1[k * 64 + j], u);
        o = fmaf(fmaxf(u, 0.f), Wc2[j], o);
    }
    out[g] = o;
}

// ---------------- launch ----------------------------------------------------
extern "C" void kernel_launch(void* const* d_in, const int* in_sizes, int n_in,
                              void* d_out, int out_size) {
    const float* x     = (const float*)d_in[0];
    const int*   ei    = (const int*)d_in[1];
    const float* eattr = (const float*)d_in[2];
    const int*   batch = (const int*)d_in[3];
    const float *W1a = (const float*)d_in[4],  *b1a = (const float*)d_in[5];
    const float *W1b = (const float*)d_in[6],  *b1b = (const float*)d_in[7];
    const float *We1 = (const float*)d_in[8],  *be1 = (const float*)d_in[9];
    const float *W2a = (const float*)d_in[10], *b2a = (const float*)d_in[11];
    const float *W2b = (const float*)d_in[12], *b2b = (const float*)d_in[13];
    const float *We2 = (const float*)d_in[14], *be2 = (const float*)d_in[15];
    const float *Wc1 = (const float*)d_in[16], *bc1 = (const float*)d_in[17];
    const float *Wc2 = (const float*)d_in[18], *bc2 = (const float*)d_in[19];
    float* out = (float*)d_out;

    int N = in_sizes[0] / DIM;
    int E = in_sizes[2];
    int G = out_size;

    const int SMEM = (4096 * 2 + 128 + 128 * 65) * (int)sizeof(float);  // ~66.5 KB
    cudaFuncSetAttribute(node_mlp, cudaFuncAttributeMaxDynamicSharedMemorySize, SMEM);

    int node_blocks = (N + 127) / 128;
    int agg_blocks  = (N * 32 + 127) / 128;
    int e_blocks    = (E + 255) / 256;
    int nb          = (N + SCAN_BLK - 1) / SCAN_BLK;   // 98

    // ---- build dst-sorted CSR + fp16 x copy (shared by both convs) ----
    zero_small<<<(N + 255) / 256, 256>>>(N);
    x2half<<<(N * 32 + 255) / 256, 256>>>(x, N * 32);
    hist_kernel<<<e_blocks, 256>>>(ei, E);
    scan_p1<<<nb, 256>>>(N);
    scan_p2<<<1, 256>>>(nb);
    scan_p3<<<nb, 256>>>(N);
    sort_scatter<<<e_blocks, 256>>>(ei, eattr, E);

    // conv1
    csr_agg16<<<agg_blocks, 128>>>(0, We1, be1, N);
    node_mlp<<<node_blocks, 128, SMEM>>>(0, x, W1a, b1a, W1b, b1b, batch, N);
    // conv2 (+ fused mean-pool sums)
    csr_agg16<<<agg_blocks, 128>>>(1, We2, be2, N);
    node_mlp<<<node_blocks, 128, SMEM>>>(1, x, W2a, b2a, W2b, b2b, batch, N);
    // classifier
    classifier<<<(G + 127) / 128, 128>>>(Wc1, bc1, Wc2, bc2, out, G);
}